// round 16
// baseline (speedup 1.0000x reference)
#include <cuda_runtime.h>
#include <cuda_bf16.h>
#include <math.h>
#include <stdint.h>

// Problem constants (fixed: ADV=8, GOOD=8, BOX=16, RAMP=8)
#define B_SZ   32768
#define HDIM   256
#define OBS    464
#define N_OTHER 15
#define N_BOX   16
#define N_RAMP  8
#define OFF_OTHER 10
#define OFF_BOX   160
#define OFF_RAMP  368

// Scratch (static device globals — allocation-free). Plain row-major layouts.
__device__ __nv_bfloat16 g_embH[(size_t)B_SZ * 256];
__device__ __nv_bfloat16 g_embL[(size_t)B_SZ * 256];
__device__ float         g_S[(size_t)B_SZ * 768];
__device__ __nv_bfloat16 g_catH[(size_t)B_SZ * 1024];
__device__ __nv_bfloat16 g_catL[(size_t)B_SZ * 1024];
__device__ __nv_bfloat16 g_hH[(size_t)B_SZ * 256];
__device__ __nv_bfloat16 g_hL[(size_t)B_SZ * 256];
__device__ float         g_hpart[(size_t)B_SZ * 256];   // e1a partial (gi @ We1[0:256])
// Weights packed [N][K] bf16 hi/lo:
__device__ __nv_bfloat16 g_Bs1H[1024 * 256];   // [corr_other|corr_box|corr_ramp|W_fc]
__device__ __nv_bfloat16 g_Bs1L[1024 * 256];
__device__ __nv_bfloat16 g_Be1H[256 * 1024];
__device__ __nv_bfloat16 g_Be1L[256 * 1024];
__device__ __nv_bfloat16 g_Be2H[256 * 256];
__device__ __nv_bfloat16 g_Be2L[256 * 256];

__device__ __forceinline__ float fast_tanh(float x) {
    float y; asm("tanh.approx.f32 %0, %1;" : "=f"(y) : "f"(x)); return y;
}
__device__ __forceinline__ uint32_t smem_u32(const void* p) {
    uint32_t a;
    asm("{ .reg .u64 t; cvta.to.shared.u64 t, %1; cvt.u32.u64 %0, t; }" : "=r"(a) : "l"(p));
    return a;
}
__device__ __forceinline__ void ldm_x4(uint32_t* r, uint32_t addr) {
    asm volatile("ldmatrix.sync.aligned.m8n8.x4.shared.b16 {%0,%1,%2,%3}, [%4];"
        : "=r"(r[0]), "=r"(r[1]), "=r"(r[2]), "=r"(r[3]) : "r"(addr));
}
__device__ __forceinline__ void mma16816(float* c, const uint32_t* a,
                                         uint32_t b0, uint32_t b1) {
    asm volatile("mma.sync.aligned.m16n8k16.row.col.f32.bf16.bf16.f32 "
        "{%0,%1,%2,%3}, {%4,%5,%6,%7}, {%8,%9}, {%0,%1,%2,%3};"
        : "+f"(c[0]), "+f"(c[1]), "+f"(c[2]), "+f"(c[3])
        : "r"(a[0]), "r"(a[1]), "r"(a[2]), "r"(a[3]), "r"(b0), "r"(b1));
}
__device__ __forceinline__ void cpa16(uint32_t s, const void* g) {
    asm volatile("cp.async.cg.shared.global [%0], [%1], 16;" :: "r"(s), "l"(g));
}
#define CPA_COMMIT() asm volatile("cp.async.commit_group;" ::: "memory")
#define CPA_WAIT1()  asm volatile("cp.async.wait_group 1;" ::: "memory")
#define CPA_WAIT0()  asm volatile("cp.async.wait_group 0;" ::: "memory")

// ---------------------------------------------------------------------------
// One launch packs all 6 weight matrices: fp32 [K,256] -> [N=256][K] bf16 hi/lo
// ---------------------------------------------------------------------------
struct PackArgs {
    const float* W[6];
    __nv_bfloat16* oh[6];
    __nv_bfloat16* ol[6];
    int K[6];
    int start[7];
};
__global__ void pack_all(PackArgs pa) {
    __shared__ float t[32][33];
    int bx = blockIdx.x;
    int job = 0;
    while (bx >= pa.start[job + 1]) ++job;
    int local = bx - pa.start[job];
    int n0 = (local & 7) * 32;
    int k0 = (local >> 3) * 32;
    int K = pa.K[job];
    const float* W = pa.W[job];
    __nv_bfloat16* oh = pa.oh[job];
    __nv_bfloat16* ol = pa.ol[job];
    int tx = threadIdx.x, ty = threadIdx.y;
    for (int r = ty; r < 32; r += 8)
        t[r][tx] = W[(size_t)(k0 + r) * 256 + n0 + tx];
    __syncthreads();
    for (int r = ty; r < 32; r += 8) {
        int n = n0 + r, k = k0 + tx;
        float x = t[tx][r];
        __nv_bfloat16 h = __float2bfloat16(x);
        oh[(size_t)n * K + k] = h;
        ol[(size_t)n * K + k] = __float2bfloat16(x - __bfloat162float(h));
    }
}

// ---------------------------------------------------------------------------
// Self embed -> packed hi/lo row-major
// ---------------------------------------------------------------------------
__global__ void self_kernel(const float* __restrict__ inputs,
                            const float* __restrict__ W,
                            const float* __restrict__ b) {
    __shared__ float Ws[10 * HDIM];
    __shared__ float bs[HDIM];
    int tid = threadIdx.x;
    for (int i = tid; i < 10 * HDIM; i += blockDim.x) Ws[i] = W[i];
    if (tid < HDIM) bs[tid] = b[tid];
    __syncthreads();

    int row0 = blockIdx.x * 4;
#pragma unroll
    for (int r = 0; r < 4; ++r) {
        int row = row0 + r;
        const float* in = inputs + (size_t)row * OBS;
        float acc = bs[tid];
#pragma unroll
        for (int f = 0; f < 10; ++f) acc += in[f] * Ws[f * HDIM + tid];
        float v = fast_tanh(acc);
        __nv_bfloat16 h = __float2bfloat16(v);
        g_embH[(size_t)row * 256 + tid] = h;
        g_embL[(size_t)row * 256 + tid] = __float2bfloat16(v - __bfloat162float(h));
    }
}

// ---------------------------------------------------------------------------
// Split-bf16 mma.sync GEMM, tile 128x128x32, 8 warps, cp.async 2-stage pipeline.
// Product-major MMA order (R15). lda/ldb separate for K-windowed operands.
// MODE 0: stage1: n0<768 -> raw fp32 S; else gi=tanh(+bias)->cat packed
// MODE 1: e1b -> tanh(acc + partial + bias) -> packed h (ld 256)
// MODE 2: e2  -> tanh(+bias) -> fp32 out (ld 256)
// MODE 3: e1a -> raw fp32 -> outF (ld 256)
// ---------------------------------------------------------------------------
#define SPAD 40
#define TILE_B 10240
#define STAGE_B (4 * TILE_B)
#define GEMM_SMEM (2 * STAGE_B)

template <int MODE>
__global__ __launch_bounds__(256)
void mma_gemm(const __nv_bfloat16* __restrict__ Ahi, const __nv_bfloat16* __restrict__ Alo,
              int lda,
              const __nv_bfloat16* __restrict__ Bhi, const __nv_bfloat16* __restrict__ Blo,
              int ldb,
              int K, int nboff,
              const float* __restrict__ bias,
              const float* __restrict__ partial,
              float* __restrict__ outF,
              __nv_bfloat16* __restrict__ outHi, __nv_bfloat16* __restrict__ outLo) {
    extern __shared__ char smem[];
    uint32_t sb = smem_u32(smem);

    int tid = threadIdx.x;
    int warp = tid >> 5, lane = tid & 31;
    int wm = warp & 3;
    int wn = warp >> 2;
    int m0 = blockIdx.y * 128;
    int n0 = (blockIdx.x + nboff) * 128;

    float acc[2][8][4];
#pragma unroll
    for (int mt = 0; mt < 2; ++mt)
#pragma unroll
        for (int nt = 0; nt < 8; ++nt)
#pragma unroll
            for (int i = 0; i < 4; ++i) acc[mt][nt][i] = 0.f;

    int aRow = wm * 32 + (lane & 15);
    int aColH = (lane >> 4) * 8;
    int bRow = wn * 64 + (lane >> 4) * 8 + (lane & 7);
    int bK8 = ((lane >> 3) & 1) * 8;

    int lrow = tid >> 1;
    int lc8a = ((tid & 1) * 2) * 8;
    int lc8b = ((tid & 1) * 2 + 1) * 8;

    auto load_tiles = [&](int t) {
        uint32_t stb = sb + (uint32_t)(t & 1) * STAGE_B;
        size_t ka = (size_t)(m0 + lrow) * lda + t * 32;
        size_t kb = (size_t)(n0 + lrow) * ldb + t * 32;
        uint32_t so = (uint32_t)(lrow * (SPAD * 2));
        cpa16(stb + so + lc8a * 2,            Ahi + ka + lc8a);
        cpa16(stb + so + lc8b * 2,            Ahi + ka + lc8b);
        cpa16(stb + TILE_B + so + lc8a * 2,   Alo + ka + lc8a);
        cpa16(stb + TILE_B + so + lc8b * 2,   Alo + ka + lc8b);
        cpa16(stb + 2*TILE_B + so + lc8a * 2, Bhi + kb + lc8a);
        cpa16(stb + 2*TILE_B + so + lc8b * 2, Bhi + kb + lc8b);
        cpa16(stb + 3*TILE_B + so + lc8a * 2, Blo + kb + lc8a);
        cpa16(stb + 3*TILE_B + so + lc8b * 2, Blo + kb + lc8b);
        CPA_COMMIT();
    };

    int nt = K >> 5;
    load_tiles(0);
    for (int t = 0; t < nt; ++t) {
        if (t + 1 < nt) { load_tiles(t + 1); CPA_WAIT1(); }
        else            { CPA_WAIT0(); }
        __syncthreads();

        uint32_t stb = sb + (uint32_t)(t & 1) * STAGE_B;
        uint32_t aBaseH = stb, aBaseL = stb + TILE_B;
        uint32_t bBaseH = stb + 2 * TILE_B, bBaseL = stb + 3 * TILE_B;

#pragma unroll
        for (int kt = 0; kt < 2; ++kt) {
            uint32_t ah[2][4], al[2][4];
#pragma unroll
            for (int mt = 0; mt < 2; ++mt) {
                uint32_t off = (uint32_t)(((aRow + mt * 16) * SPAD + kt * 16 + aColH) * 2);
                ldm_x4(ah[mt], aBaseH + off);
                ldm_x4(al[mt], aBaseL + off);
            }
#pragma unroll
            for (int nt2 = 0; nt2 < 4; ++nt2) {
                uint32_t bh[4], bl[4];
                uint32_t off = (uint32_t)(((bRow + nt2 * 16) * SPAD + kt * 16 + bK8) * 2);
                ldm_x4(bh, bBaseH + off);
                ldm_x4(bl, bBaseL + off);
                // product-major order: 4 distinct accumulators between reuses
                mma16816(acc[0][nt2 * 2],     ah[0], bh[0], bh[1]);
                mma16816(acc[0][nt2 * 2 + 1], ah[0], bh[2], bh[3]);
                mma16816(acc[1][nt2 * 2],     ah[1], bh[0], bh[1]);
                mma16816(acc[1][nt2 * 2 + 1], ah[1], bh[2], bh[3]);
                mma16816(acc[0][nt2 * 2],     ah[0], bl[0], bl[1]);
                mma16816(acc[0][nt2 * 2 + 1], ah[0], bl[2], bl[3]);
                mma16816(acc[1][nt2 * 2],     ah[1], bl[0], bl[1]);
                mma16816(acc[1][nt2 * 2 + 1], ah[1], bl[2], bl[3]);
                mma16816(acc[0][nt2 * 2],     al[0], bh[0], bh[1]);
                mma16816(acc[0][nt2 * 2 + 1], al[0], bh[2], bh[3]);
                mma16816(acc[1][nt2 * 2],     al[1], bh[0], bh[1]);
                mma16816(acc[1][nt2 * 2 + 1], al[1], bh[2], bh[3]);
            }
        }
        __syncthreads();
    }

    bool rawS = (MODE == 0) && (n0 < 768);
#pragma unroll
    for (int mt = 0; mt < 2; ++mt) {
#pragma unroll
        for (int nt = 0; nt < 8; ++nt) {
            int r0 = m0 + wm * 32 + mt * 16 + (lane >> 2);
            int col = n0 + wn * 64 + nt * 8 + (lane & 3) * 2;
#pragma unroll
            for (int half = 0; half < 2; ++half) {
                int row = r0 + half * 8;
                float c0 = acc[mt][nt][half * 2], c1 = acc[mt][nt][half * 2 + 1];
                if (rawS) {
                    *(float2*)(outF + (size_t)row * 768 + col) = make_float2(c0, c1);
                } else if (MODE == 3) {
                    *(float2*)(outF + (size_t)row * 256 + col) = make_float2(c0, c1);
                } else if (MODE == 2) {
                    float2 bv = *(const float2*)(bias + col);
                    *(float2*)(outF + (size_t)row * 256 + col) =
                        make_float2(fast_tanh(c0 + bv.x), fast_tanh(c1 + bv.y));
                } else if (MODE == 1) {
                    float2 bv = *(const float2*)(bias + col);
                    float2 pv = *(const float2*)(partial + (size_t)row * 256 + col);
                    float f0 = fast_tanh(c0 + pv.x + bv.x);
                    float f1 = fast_tanh(c1 + pv.y + bv.y);
                    __nv_bfloat16 h0 = __float2bfloat16(f0);
                    __nv_bfloat16 h1 = __float2bfloat16(f1);
                    __nv_bfloat162 hv; hv.x = h0; hv.y = h1;
                    __nv_bfloat162 lv;
                    lv.x = __float2bfloat16(f0 - __bfloat162float(h0));
                    lv.y = __float2bfloat16(f1 - __bfloat162float(h1));
                    *(__nv_bfloat162*)(outHi + (size_t)row * 256 + col) = hv;
                    *(__nv_bfloat162*)(outLo + (size_t)row * 256 + col) = lv;
                } else {  // MODE 0 gi
                    int oc = col - 768;
                    float2 bv = *(const float2*)(bias + oc);
                    float f0 = fast_tanh(c0 + bv.x);
                    float f1 = fast_tanh(c1 + bv.y);
                    __nv_bfloat16 h0 = __float2bfloat16(f0);
                    __nv_bfloat16 h1 = __float2bfloat16(f1);
                    __nv_bfloat162 hv; hv.x = h0; hv.y = h1;
                    __nv_bfloat162 lv;
                    lv.x = __float2bfloat16(f0 - __bfloat162float(h0));
                    lv.y = __float2bfloat16(f1 - __bfloat162float(h1));
                    *(__nv_bfloat162*)(outHi + (size_t)row * 1024 + oc) = hv;
                    *(__nv_bfloat162*)(outLo + (size_t)row * 1024 + oc) = lv;
                }
            }
        }
    }
}

// ---------------------------------------------------------------------------
// Unified scalar attention (proven R12 version): 3 groups in one launch.
// ---------------------------------------------------------------------------
template <int NENT, int FDIM, int IN_OFF, int GOFF, int CAT_OFF>
__device__ __forceinline__
void attn_body(const float* __restrict__ inputs, const float* __restrict__ S,
               const float* __restrict__ W, const float* __restrict__ bias,
               int bid, float (*sfeat)[208], float* sred) {
    constexpr int FT = NENT * FDIM;
    constexpr int FHALF = FT / 2;
    constexpr int NPAIR = NENT / 2;

    int tid = threadIdx.x;
    int warp = tid >> 5, lane = tid & 31;
    int slot = warp >> 1;
    int half = warp & 1;

    float wreg[4][FDIM], breg[4];
#pragma unroll
    for (int j = 0; j < 4; ++j) {
        int h = j * 64 + half * 32 + lane;
        breg[j] = __ldg(bias + h);
#pragma unroll
        for (int f = 0; f < FDIM; ++f)
            wreg[j][f] = __ldg(W + f * HDIM + h);
    }

    for (int row0 = bid * 4; row0 < B_SZ; row0 += 4096) {
        int row = row0 + slot;
        {
            const float* rowin = inputs + (size_t)row * OBS + IN_OFF;
            int lo = half * FHALF;
            int hi = half ? FT : FHALF;
            for (int i = lo + lane; i < hi; i += 32)
                sfeat[slot][i] = rowin[i];
        }
        __syncthreads();

        float s[4], acc[4];
#pragma unroll
        for (int j = 0; j < 4; ++j) {
            s[j] = S[(size_t)row * 768 + GOFF + j * 64 + half * 32 + lane];
            acc[j] = 0.f;
        }
        float l = 0.f;

#pragma unroll 1
        for (int np = 0; np < NPAIR; ++np) {
            int n = np * 2;
            const float* f0 = &sfeat[slot][n * FDIM];
            const float* f1 = f0 + FDIM;
            float e0[4], e1[4];
#pragma unroll
            for (int j = 0; j < 4; ++j) {
                float a0 = breg[j], a1 = breg[j];
#pragma unroll
                for (int f = 0; f < FDIM; ++f) {
                    a0 += f0[f] * wreg[j][f];
                    a1 += f1[f] * wreg[j][f];
                }
                e0[j] = fast_tanh(a0);
                e1[j] = fast_tanh(a1);
            }
            float p0 = 0.f, p1 = 0.f;
#pragma unroll
            for (int j = 0; j < 4; ++j) { p0 += s[j] * e0[j]; p1 += s[j] * e1[j]; }
#pragma unroll
            for (int off = 16; off > 0; off >>= 1) {
                p0 += __shfl_xor_sync(0xFFFFFFFFu, p0, off);
                p1 += __shfl_xor_sync(0xFFFFFFFFu, p1, off);
            }
            int pp = np & 1;
            if (lane == 0) {
                sred[((pp * 2 + 0) * 2 + half) * 4 + slot] = p0;
                sred[((pp * 2 + 1) * 2 + half) * 4 + slot] = p1;
            }
            __syncthreads();
            float bp0 = sred[((pp * 2 + 0) * 2 + 0) * 4 + slot] +
                        sred[((pp * 2 + 0) * 2 + 1) * 4 + slot];
            float bp1 = sred[((pp * 2 + 1) * 2 + 0) * 4 + slot] +
                        sred[((pp * 2 + 1) * 2 + 1) * 4 + slot];
            float w0 = __expf(bp0), w1 = __expf(bp1);
            l += w0 + w1;
#pragma unroll
            for (int j = 0; j < 4; ++j) acc[j] += w0 * e0[j] + w1 * e1[j];
        }

        if (NENT & 1) {  // tail entity
            int n = NENT - 1;
            const float* ft = &sfeat[slot][n * FDIM];
            float e0[4];
#pragma unroll
            for (int j = 0; j < 4; ++j) {
                float a = breg[j];
#pragma unroll
                for (int f = 0; f < FDIM; ++f) a += ft[f] * wreg[j][f];
                e0[j] = fast_tanh(a);
            }
            float p0 = 0.f;
#pragma unroll
            for (int j = 0; j < 4; ++j) p0 += s[j] * e0[j];
#pragma unroll
            for (int off = 16; off > 0; off >>= 1)
                p0 += __shfl_xor_sync(0xFFFFFFFFu, p0, off);
            int pp = NPAIR & 1;
            if (lane == 0) sred[((pp * 2 + 0) * 2 + half) * 4 + slot] = p0;
            __syncthreads();
            float bp0 = sred[((pp * 2 + 0) * 2 + 0) * 4 + slot] +
                        sred[((pp * 2 + 0) * 2 + 1) * 4 + slot];
            float w0 = __expf(bp0);
            l += w0;
#pragma unroll
            for (int j = 0; j < 4; ++j) acc[j] += w0 * e0[j];
        }

        float inv = 1.f / l;
#pragma unroll
        for (int j = 0; j < 4; ++j) {
            float f = acc[j] * inv;
            int col = CAT_OFF + j * 64 + half * 32 + lane;
            __nv_bfloat16 h = __float2bfloat16(f);
            g_catH[(size_t)row * 1024 + col] = h;
            g_catL[(size_t)row * 1024 + col] = __float2bfloat16(f - __bfloat162float(h));
        }
        __syncthreads();   // protect sfeat/sred reuse across row iterations
    }
}

__global__ __launch_bounds__(256, 2)
void attn_all(const float* __restrict__ inputs, const float* __restrict__ S,
              const float* __restrict__ Wo, const float* __restrict__ bo,
              const float* __restrict__ Wb, const float* __restrict__ bb,
              const float* __restrict__ Wr, const float* __restrict__ br) {
    __shared__ float sfeat[4][208];
    __shared__ float sred[32];
    int grp = blockIdx.x >> 10;
    int bid = blockIdx.x & 1023;
    if (grp == 0)
        attn_body<N_OTHER, 10, OFF_OTHER, 0,   256>(inputs, S, Wo, bo, bid, sfeat, sred);
    else if (grp == 1)
        attn_body<N_BOX,   13, OFF_BOX,   256, 512>(inputs, S, Wb, bb, bid, sfeat, sred);
    else
        attn_body<N_RAMP,  12, OFF_RAMP,  512, 768>(inputs, S, Wr, br, bid, sfeat, sred);
}

// ---------------------------------------------------------------------------
extern "C" void kernel_launch(void* const* d_in, const int* in_sizes, int n_in,
                              void* d_out, int out_size) {
    const float* inputs     = (const float*)d_in[0];
    const float* W_self     = (const float*)d_in[1];
    const float* b_self     = (const float*)d_in[2];
    const float* W_other    = (const float*)d_in[3];
    const float* b_other    = (const float*)d_in[4];
    const float* W_box      = (const float*)d_in[5];
    const float* b_box      = (const float*)d_in[6];
    const float* W_ramp     = (const float*)d_in[7];
    const float* b_ramp     = (const float*)d_in[8];
    const float* corr_other = (const float*)d_in[9];
    const float* corr_box   = (const float*)d_in[10];
    const float* corr_ramp  = (const float*)d_in[11];
    const float* W_fc       = (const float*)d_in[12];
    const float* b_fc       = (const float*)d_in[13];
    const float* W_e1       = (const float*)d_in[14];
    const float* b_e1       = (const float*)d_in[15];
    const float* W_e2       = (const float*)d_in[16];
    const float* b_e2       = (const float*)d_in[17];
    float* out = (float*)d_out;

    __nv_bfloat16 *embH, *embL, *catH, *catL, *hH, *hL;
    __nv_bfloat16 *Bs1H, *Bs1L, *Be1H, *Be1L, *Be2H, *Be2L;
    float *S, *hpart;
    cudaGetSymbolAddress((void**)&embH, g_embH);
    cudaGetSymbolAddress((void**)&embL, g_embL);
    cudaGetSymbolAddress((void**)&S,    g_S);
    cudaGetSymbolAddress((void**)&catH, g_catH);
    cudaGetSymbolAddress((void**)&catL, g_catL);
    cudaGetSymbolAddress((void**)&hH,   g_hH);
    cudaGetSymbolAddress((void**)&hL,   g_hL);
    cudaGetSymbolAddress((void**)&hpart, g_hpart);
    cudaGetSymbolAddress((void**)&Bs1H, g_Bs1H);
    cudaGetSymbolAddress((void**)&Bs1L, g_Bs1L);
    cudaGetSymbolAddress((void**)&Be1H, g_Be1H);
    cudaGetSymbolAddress((void**)&Be1L, g_Be1L);
    cudaGetSymbolAddress((void**)&Be2H, g_Be2H);
    cudaGetSymbolAddress((void**)&Be2L, g_Be2L);

    cudaFuncSetAttribute(mma_gemm<0>, cudaFuncAttributeMaxDynamicSharedMemorySize, GEMM_SMEM);
    cudaFuncSetAttribute(mma_gemm<1>, cudaFuncAttributeMaxDynamicSharedMemorySize, GEMM_SMEM);
    cudaFuncSetAttribute(mma_gemm<2>, cudaFuncAttributeMaxDynamicSharedMemorySize, GEMM_SMEM);
    cudaFuncSetAttribute(mma_gemm<3>, cudaFuncAttributeMaxDynamicSharedMemorySize, GEMM_SMEM);

    // One-time stream/event creation (no device memory involved).
    static cudaStream_t s1 = nullptr;
    static cudaEvent_t e0 = nullptr, ePack = nullptr, eSelf = nullptr, eE1a = nullptr;
    if (s1 == nullptr) {
        cudaStreamCreateWithFlags(&s1, cudaStreamNonBlocking);
        cudaEventCreateWithFlags(&e0,    cudaEventDisableTiming);
        cudaEventCreateWithFlags(&ePack, cudaEventDisableTiming);
        cudaEventCreateWithFlags(&eSelf, cudaEventDisableTiming);
        cudaEventCreateWithFlags(&eE1a,  cudaEventDisableTiming);
    }

    PackArgs pa;
    pa.W[0] = corr_other; pa.oh[0] = Bs1H + 0 * 65536; pa.ol[0] = Bs1L + 0 * 65536; pa.K[0] = 256;
    pa.W[1] = corr_box;   pa.oh[1] = Bs1H + 1 * 65536; pa.ol[1] = Bs1L + 1 * 65536; pa.K[1] = 256;
    pa.W[2] = corr_ramp;  pa.oh[2] = Bs1H + 2 * 65536; pa.ol[2] = Bs1L + 2 * 65536; pa.K[2] = 256;
    pa.W[3] = W_fc;       pa.oh[3] = Bs1H + 3 * 65536; pa.ol[3] = Bs1L + 3 * 65536; pa.K[3] = 256;
    pa.W[4] = W_e1;       pa.oh[4] = Be1H;             pa.ol[4] = Be1L;             pa.K[4] = 1024;
    pa.W[5] = W_e2;       pa.oh[5] = Be2H;             pa.ol[5] = Be2L;             pa.K[5] = 256;
    pa.start[0] = 0;   pa.start[1] = 64;  pa.start[2] = 128; pa.start[3] = 192;
    pa.start[4] = 256; pa.start[5] = 512; pa.start[6] = 576;

    // Fork s1 from the capture stream.
    cudaEventRecord(e0, 0);
    cudaStreamWaitEvent(s1, e0, 0);

    // s1: pack weights (independent of self embed)
    pack_all<<<576, dim3(32, 8), 0, s1>>>(pa);
    cudaEventRecord(ePack, s1);

    // s0: self embed
    self_kernel<<<B_SZ / 4, 256>>>(inputs, W_self, b_self);
    cudaEventRecord(eSelf, 0);

    dim3 g2(2, B_SZ / 128);

    // s1: gi part of stage1 (cols 768..1024) — needs pack (in-stream) + self
    cudaStreamWaitEvent(s1, eSelf, 0);
    mma_gemm<0><<<g2, 256, GEMM_SMEM, s1>>>(
        embH, embL, 256, Bs1H, Bs1L, 256, 256, /*nboff*/6, b_fc, nullptr, S, catH, catL);

    // s1: e1a = gi @ We1[0:256] -> hpart (raw fp32) — runs during attn
    mma_gemm<3><<<g2, 256, GEMM_SMEM, s1>>>(
        catH, catL, 1024, Be1H, Be1L, 1024, 256, 0, nullptr, nullptr, hpart, nullptr, nullptr);
    cudaEventRecord(eE1a, s1);

    // s0: S part of stage1 (cols 0..768) — needs pack
    cudaStreamWaitEvent(0, ePack, 0);
    mma_gemm<0><<<dim3(6, B_SZ / 128), 256, GEMM_SMEM>>>(
        embH, embL, 256, Bs1H, Bs1L, 256, 256, /*nboff*/0, b_fc, nullptr, S, catH, catL);

    // s0: scalar attention (concurrent with s1's gi + e1a)
    attn_all<<<3072, 256>>>(inputs, S, W_other, b_other, W_box, b_box, W_ramp, b_ramp);

    // s0: e1b = vi @ We1[256:1024] + hpart -> h ; then e2
    cudaStreamWaitEvent(0, eE1a, 0);
    mma_gemm<1><<<g2, 256, GEMM_SMEM>>>(
        catH + 256, catL + 256, 1024, Be1H + 256, Be1L + 256, 1024, 768, 0,
        b_e1, hpart, nullptr, hH, hL);
    mma_gemm<2><<<g2, 256, GEMM_SMEM>>>(
        hH, hL, 256, Be2H, Be2L, 256, 256, 0, b_e2, nullptr, out, nullptr, nullptr);
}

// round 17
// speedup vs baseline: 1.0505x; 1.0505x over previous
#include <cuda_runtime.h>
#include <cuda_bf16.h>
#include <math.h>
#include <stdint.h>

// Problem constants (fixed: ADV=8, GOOD=8, BOX=16, RAMP=8)
#define B_SZ   32768
#define HDIM   256
#define OBS    464
#define N_OTHER 15
#define N_BOX   16
#define N_RAMP  8
#define OFF_OTHER 10
#define OFF_BOX   160
#define OFF_RAMP  368

// Scratch (static device globals — allocation-free). Plain row-major layouts.
__device__ __nv_bfloat16 g_embH[(size_t)B_SZ * 256];
__device__ __nv_bfloat16 g_embL[(size_t)B_SZ * 256];
__device__ float         g_S[(size_t)B_SZ * 768];
__device__ __nv_bfloat16 g_catH[(size_t)B_SZ * 1024];
__device__ __nv_bfloat16 g_catL[(size_t)B_SZ * 1024];
__device__ __nv_bfloat16 g_hH[(size_t)B_SZ * 256];
__device__ __nv_bfloat16 g_hL[(size_t)B_SZ * 256];
// Weights packed [N][K] bf16 hi/lo:
__device__ __nv_bfloat16 g_Bs1H[1024 * 256];   // [corr_other|corr_box|corr_ramp|W_fc]
__device__ __nv_bfloat16 g_Bs1L[1024 * 256];
__device__ __nv_bfloat16 g_Be1H[256 * 1024];
__device__ __nv_bfloat16 g_Be1L[256 * 1024];
__device__ __nv_bfloat16 g_Be2H[256 * 256];
__device__ __nv_bfloat16 g_Be2L[256 * 256];

__device__ __forceinline__ float fast_tanh(float x) {
    float y; asm("tanh.approx.f32 %0, %1;" : "=f"(y) : "f"(x)); return y;
}
__device__ __forceinline__ uint32_t smem_u32(const void* p) {
    uint32_t a;
    asm("{ .reg .u64 t; cvta.to.shared.u64 t, %1; cvt.u32.u64 %0, t; }" : "=r"(a) : "l"(p));
    return a;
}
__device__ __forceinline__ void ldm_x4(uint32_t* r, uint32_t addr) {
    asm volatile("ldmatrix.sync.aligned.m8n8.x4.shared.b16 {%0,%1,%2,%3}, [%4];"
        : "=r"(r[0]), "=r"(r[1]), "=r"(r[2]), "=r"(r[3]) : "r"(addr));
}
__device__ __forceinline__ void mma16816(float* c, const uint32_t* a,
                                         uint32_t b0, uint32_t b1) {
    asm volatile("mma.sync.aligned.m16n8k16.row.col.f32.bf16.bf16.f32 "
        "{%0,%1,%2,%3}, {%4,%5,%6,%7}, {%8,%9}, {%0,%1,%2,%3};"
        : "+f"(c[0]), "+f"(c[1]), "+f"(c[2]), "+f"(c[3])
        : "r"(a[0]), "r"(a[1]), "r"(a[2]), "r"(a[3]), "r"(b0), "r"(b1));
}
__device__ __forceinline__ void cpa16(uint32_t s, const void* g) {
    asm volatile("cp.async.cg.shared.global [%0], [%1], 16;" :: "r"(s), "l"(g));
}
#define CPA_COMMIT() asm volatile("cp.async.commit_group;" ::: "memory")
#define CPA_WAIT1()  asm volatile("cp.async.wait_group 1;" ::: "memory")
#define CPA_WAIT0()  asm volatile("cp.async.wait_group 0;" ::: "memory")

// ---------------------------------------------------------------------------
// One launch packs all 6 weight matrices: fp32 [K,256] -> [N=256][K] bf16 hi/lo
// ---------------------------------------------------------------------------
struct PackArgs {
    const float* W[6];
    __nv_bfloat16* oh[6];
    __nv_bfloat16* ol[6];
    int K[6];
    int start[7];
};
__global__ void pack_all(PackArgs pa) {
    __shared__ float t[32][33];
    int bx = blockIdx.x;
    int job = 0;
    while (bx >= pa.start[job + 1]) ++job;
    int local = bx - pa.start[job];
    int n0 = (local & 7) * 32;
    int k0 = (local >> 3) * 32;
    int K = pa.K[job];
    const float* W = pa.W[job];
    __nv_bfloat16* oh = pa.oh[job];
    __nv_bfloat16* ol = pa.ol[job];
    int tx = threadIdx.x, ty = threadIdx.y;
    for (int r = ty; r < 32; r += 8)
        t[r][tx] = W[(size_t)(k0 + r) * 256 + n0 + tx];
    __syncthreads();
    for (int r = ty; r < 32; r += 8) {
        int n = n0 + r, k = k0 + tx;
        float x = t[tx][r];
        __nv_bfloat16 h = __float2bfloat16(x);
        oh[(size_t)n * K + k] = h;
        ol[(size_t)n * K + k] = __float2bfloat16(x - __bfloat162float(h));
    }
}

// ---------------------------------------------------------------------------
// Self embed -> packed hi/lo row-major
// ---------------------------------------------------------------------------
__global__ void self_kernel(const float* __restrict__ inputs,
                            const float* __restrict__ W,
                            const float* __restrict__ b) {
    __shared__ float Ws[10 * HDIM];
    __shared__ float bs[HDIM];
    int tid = threadIdx.x;
    for (int i = tid; i < 10 * HDIM; i += blockDim.x) Ws[i] = W[i];
    if (tid < HDIM) bs[tid] = b[tid];
    __syncthreads();

    int row0 = blockIdx.x * 4;
#pragma unroll
    for (int r = 0; r < 4; ++r) {
        int row = row0 + r;
        const float* in = inputs + (size_t)row * OBS;
        float acc = bs[tid];
#pragma unroll
        for (int f = 0; f < 10; ++f) acc += in[f] * Ws[f * HDIM + tid];
        float v = fast_tanh(acc);
        __nv_bfloat16 h = __float2bfloat16(v);
        g_embH[(size_t)row * 256 + tid] = h;
        g_embL[(size_t)row * 256 + tid] = __float2bfloat16(v - __bfloat162float(h));
    }
}

// ---------------------------------------------------------------------------
// Split-bf16 mma.sync GEMM, tile 128x128x32, 8 warps, cp.async 2-stage pipeline.
// Product-major MMA order. n0 = (blockIdx.x + nboff)*128.
// MODE 0: stage1: n0<768 -> raw fp32 S; else gi=tanh(+bias)->cat packed
// MODE 1: e1 -> tanh(+bias) -> h packed; MODE 2: e2 -> fp32 out
// ---------------------------------------------------------------------------
#define SPAD 40
#define TILE_B 10240
#define STAGE_B (4 * TILE_B)
#define GEMM_SMEM (2 * STAGE_B)

template <int MODE>
__global__ __launch_bounds__(256)
void mma_gemm(const __nv_bfloat16* __restrict__ Ahi, const __nv_bfloat16* __restrict__ Alo,
              const __nv_bfloat16* __restrict__ Bhi, const __nv_bfloat16* __restrict__ Blo,
              int K, int nboff,
              const float* __restrict__ bias,
              float* __restrict__ outF,
              __nv_bfloat16* __restrict__ outHi, __nv_bfloat16* __restrict__ outLo) {
    extern __shared__ char smem[];
    uint32_t sb = smem_u32(smem);

    int tid = threadIdx.x;
    int warp = tid >> 5, lane = tid & 31;
    int wm = warp & 3;
    int wn = warp >> 2;
    int m0 = blockIdx.y * 128;
    int n0 = (blockIdx.x + nboff) * 128;

    float acc[2][8][4];
#pragma unroll
    for (int mt = 0; mt < 2; ++mt)
#pragma unroll
        for (int nt = 0; nt < 8; ++nt)
#pragma unroll
            for (int i = 0; i < 4; ++i) acc[mt][nt][i] = 0.f;

    int aRow = wm * 32 + (lane & 15);
    int aColH = (lane >> 4) * 8;
    int bRow = wn * 64 + (lane >> 4) * 8 + (lane & 7);
    int bK8 = ((lane >> 3) & 1) * 8;

    int lrow = tid >> 1;
    int lc8a = ((tid & 1) * 2) * 8;
    int lc8b = ((tid & 1) * 2 + 1) * 8;

    auto load_tiles = [&](int t) {
        uint32_t stb = sb + (uint32_t)(t & 1) * STAGE_B;
        size_t ka = (size_t)(m0 + lrow) * K + t * 32;
        size_t kb = (size_t)(n0 + lrow) * K + t * 32;
        uint32_t so = (uint32_t)(lrow * (SPAD * 2));
        cpa16(stb + so + lc8a * 2,            Ahi + ka + lc8a);
        cpa16(stb + so + lc8b * 2,            Ahi + ka + lc8b);
        cpa16(stb + TILE_B + so + lc8a * 2,   Alo + ka + lc8a);
        cpa16(stb + TILE_B + so + lc8b * 2,   Alo + ka + lc8b);
        cpa16(stb + 2*TILE_B + so + lc8a * 2, Bhi + kb + lc8a);
        cpa16(stb + 2*TILE_B + so + lc8b * 2, Bhi + kb + lc8b);
        cpa16(stb + 3*TILE_B + so + lc8a * 2, Blo + kb + lc8a);
        cpa16(stb + 3*TILE_B + so + lc8b * 2, Blo + kb + lc8b);
        CPA_COMMIT();
    };

    int nt = K >> 5;
    load_tiles(0);
    for (int t = 0; t < nt; ++t) {
        if (t + 1 < nt) { load_tiles(t + 1); CPA_WAIT1(); }
        else            { CPA_WAIT0(); }
        __syncthreads();

        uint32_t stb = sb + (uint32_t)(t & 1) * STAGE_B;
        uint32_t aBaseH = stb, aBaseL = stb + TILE_B;
        uint32_t bBaseH = stb + 2 * TILE_B, bBaseL = stb + 3 * TILE_B;

#pragma unroll
        for (int kt = 0; kt < 2; ++kt) {
            uint32_t ah[2][4], al[2][4];
#pragma unroll
            for (int mt = 0; mt < 2; ++mt) {
                uint32_t off = (uint32_t)(((aRow + mt * 16) * SPAD + kt * 16 + aColH) * 2);
                ldm_x4(ah[mt], aBaseH + off);
                ldm_x4(al[mt], aBaseL + off);
            }
#pragma unroll
            for (int nt2 = 0; nt2 < 4; ++nt2) {
                uint32_t bh[4], bl[4];
                uint32_t off = (uint32_t)(((bRow + nt2 * 16) * SPAD + kt * 16 + bK8) * 2);
                ldm_x4(bh, bBaseH + off);
                ldm_x4(bl, bBaseL + off);
                mma16816(acc[0][nt2 * 2],     ah[0], bh[0], bh[1]);
                mma16816(acc[0][nt2 * 2 + 1], ah[0], bh[2], bh[3]);
                mma16816(acc[1][nt2 * 2],     ah[1], bh[0], bh[1]);
                mma16816(acc[1][nt2 * 2 + 1], ah[1], bh[2], bh[3]);
                mma16816(acc[0][nt2 * 2],     ah[0], bl[0], bl[1]);
                mma16816(acc[0][nt2 * 2 + 1], ah[0], bl[2], bl[3]);
                mma16816(acc[1][nt2 * 2],     ah[1], bl[0], bl[1]);
                mma16816(acc[1][nt2 * 2 + 1], ah[1], bl[2], bl[3]);
                mma16816(acc[0][nt2 * 2],     al[0], bh[0], bh[1]);
                mma16816(acc[0][nt2 * 2 + 1], al[0], bh[2], bh[3]);
                mma16816(acc[1][nt2 * 2],     al[1], bh[0], bh[1]);
                mma16816(acc[1][nt2 * 2 + 1], al[1], bh[2], bh[3]);
            }
        }
        __syncthreads();
    }

    bool rawS = (MODE == 0) && (n0 < 768);
#pragma unroll
    for (int mt = 0; mt < 2; ++mt) {
#pragma unroll
        for (int nt = 0; nt < 8; ++nt) {
            int r0 = m0 + wm * 32 + mt * 16 + (lane >> 2);
            int col = n0 + wn * 64 + nt * 8 + (lane & 3) * 2;
#pragma unroll
            for (int half = 0; half < 2; ++half) {
                int row = r0 + half * 8;
                float c0 = acc[mt][nt][half * 2], c1 = acc[mt][nt][half * 2 + 1];
                if (rawS) {
                    *(float2*)(outF + (size_t)row * 768 + col) = make_float2(c0, c1);
                } else if (MODE == 2) {
                    float2 bv = *(const float2*)(bias + col);
                    *(float2*)(outF + (size_t)row * 256 + col) =
                        make_float2(fast_tanh(c0 + bv.x), fast_tanh(c1 + bv.y));
                } else {
                    int oc = (MODE == 0) ? (col - 768) : col;
                    int ldo = (MODE == 0) ? 1024 : 256;
                    float2 bv = *(const float2*)(bias + oc);
                    float f0 = fast_tanh(c0 + bv.x);
                    float f1 = fast_tanh(c1 + bv.y);
                    __nv_bfloat16 h0 = __float2bfloat16(f0);
                    __nv_bfloat16 h1 = __float2bfloat16(f1);
                    __nv_bfloat162 hv; hv.x = h0; hv.y = h1;
                    __nv_bfloat162 lv;
                    lv.x = __float2bfloat16(f0 - __bfloat162float(h0));
                    lv.y = __float2bfloat16(f1 - __bfloat162float(h1));
                    int ocol = (MODE == 0) ? oc : col;
                    *(__nv_bfloat162*)(outHi + (size_t)row * ldo + ocol) = hv;
                    *(__nv_bfloat162*)(outLo + (size_t)row * ldo + ocol) = lv;
                }
            }
        }
    }
}

// ---------------------------------------------------------------------------
// Unified scalar attention v6: QUAD entity batching per barrier round.
// 4 independent shuffle chains interleave; barrier count halves vs pairs.
// Warp-pair per row, register-resident W, no online softmax.
// ---------------------------------------------------------------------------
template <int NENT, int FDIM, int IN_OFF, int GOFF, int CAT_OFF>
__device__ __forceinline__
void attn_body(const float* __restrict__ inputs, const float* __restrict__ S,
               const float* __restrict__ W, const float* __restrict__ bias,
               int bid, float (*sfeat)[208], float* sred) {
    constexpr int FT = NENT * FDIM;
    constexpr int FHALF = FT / 2;
    constexpr int NQUAD = NENT / 4;
    constexpr bool HAS_PAIR = (NENT % 4) >= 2;
    constexpr bool HAS_TAIL = (NENT % 2) == 1;

    int tid = threadIdx.x;
    int warp = tid >> 5, lane = tid & 31;
    int slot = warp >> 1;
    int half = warp & 1;

    float wreg[4][FDIM], breg[4];
#pragma unroll
    for (int j = 0; j < 4; ++j) {
        int h = j * 64 + half * 32 + lane;
        breg[j] = __ldg(bias + h);
#pragma unroll
        for (int f = 0; f < FDIM; ++f)
            wreg[j][f] = __ldg(W + f * HDIM + h);
    }

    // sred index: ((pp*4 + which)*2 + half)*4 + slot   (pp = round parity)
    for (int row0 = bid * 4; row0 < B_SZ; row0 += 4096) {
        int row = row0 + slot;
        {
            const float* rowin = inputs + (size_t)row * OBS + IN_OFF;
            int lo = half * FHALF;
            int hi = half ? FT : FHALF;
            for (int i = lo + lane; i < hi; i += 32)
                sfeat[slot][i] = rowin[i];
        }
        __syncthreads();

        float s[4], acc[4];
#pragma unroll
        for (int j = 0; j < 4; ++j) {
            s[j] = S[(size_t)row * 768 + GOFF + j * 64 + half * 32 + lane];
            acc[j] = 0.f;
        }
        float l = 0.f;

#pragma unroll 1
        for (int q = 0; q < NQUAD; ++q) {
            int n = q * 4;
            const float* f0 = &sfeat[slot][(n + 0) * FDIM];
            const float* f1 = &sfeat[slot][(n + 1) * FDIM];
            const float* f2 = &sfeat[slot][(n + 2) * FDIM];
            const float* f3 = &sfeat[slot][(n + 3) * FDIM];
            float e0[4], e1[4], e2[4], e3[4];
#pragma unroll
            for (int j = 0; j < 4; ++j) {
                float a0 = breg[j], a1 = breg[j], a2 = breg[j], a3 = breg[j];
#pragma unroll
                for (int f = 0; f < FDIM; ++f) {
                    float w = wreg[j][f];
                    a0 += f0[f] * w;
                    a1 += f1[f] * w;
                    a2 += f2[f] * w;
                    a3 += f3[f] * w;
                }
                e0[j] = fast_tanh(a0);
                e1[j] = fast_tanh(a1);
                e2[j] = fast_tanh(a2);
                e3[j] = fast_tanh(a3);
            }
            float p0 = 0.f, p1 = 0.f, p2 = 0.f, p3 = 0.f;
#pragma unroll
            for (int j = 0; j < 4; ++j) {
                p0 += s[j] * e0[j]; p1 += s[j] * e1[j];
                p2 += s[j] * e2[j]; p3 += s[j] * e3[j];
            }
#pragma unroll
            for (int off = 16; off > 0; off >>= 1) {
                p0 += __shfl_xor_sync(0xFFFFFFFFu, p0, off);
                p1 += __shfl_xor_sync(0xFFFFFFFFu, p1, off);
                p2 += __shfl_xor_sync(0xFFFFFFFFu, p2, off);
                p3 += __shfl_xor_sync(0xFFFFFFFFu, p3, off);
            }
            int pp = q & 1;
            if (lane == 0) {
                sred[((pp * 4 + 0) * 2 + half) * 4 + slot] = p0;
                sred[((pp * 4 + 1) * 2 + half) * 4 + slot] = p1;
                sred[((pp * 4 + 2) * 2 + half) * 4 + slot] = p2;
                sred[((pp * 4 + 3) * 2 + half) * 4 + slot] = p3;
            }
            __syncthreads();
            float bp0 = sred[((pp * 4 + 0) * 2 + 0) * 4 + slot] + sred[((pp * 4 + 0) * 2 + 1) * 4 + slot];
            float bp1 = sred[((pp * 4 + 1) * 2 + 0) * 4 + slot] + sred[((pp * 4 + 1) * 2 + 1) * 4 + slot];
            float bp2 = sred[((pp * 4 + 2) * 2 + 0) * 4 + slot] + sred[((pp * 4 + 2) * 2 + 1) * 4 + slot];
            float bp3 = sred[((pp * 4 + 3) * 2 + 0) * 4 + slot] + sred[((pp * 4 + 3) * 2 + 1) * 4 + slot];
            float w0 = __expf(bp0), w1 = __expf(bp1);
            float w2 = __expf(bp2), w3 = __expf(bp3);
            l += w0 + w1 + w2 + w3;
#pragma unroll
            for (int j = 0; j < 4; ++j)
                acc[j] += w0 * e0[j] + w1 * e1[j] + w2 * e2[j] + w3 * e3[j];
        }

        if (HAS_PAIR) {   // entities NQUAD*4, +1
            int n = NQUAD * 4;
            const float* f0 = &sfeat[slot][n * FDIM];
            const float* f1 = f0 + FDIM;
            float e0[4], e1[4];
#pragma unroll
            for (int j = 0; j < 4; ++j) {
                float a0 = breg[j], a1 = breg[j];
#pragma unroll
                for (int f = 0; f < FDIM; ++f) {
                    a0 += f0[f] * wreg[j][f];
                    a1 += f1[f] * wreg[j][f];
                }
                e0[j] = fast_tanh(a0);
                e1[j] = fast_tanh(a1);
            }
            float p0 = 0.f, p1 = 0.f;
#pragma unroll
            for (int j = 0; j < 4; ++j) { p0 += s[j] * e0[j]; p1 += s[j] * e1[j]; }
#pragma unroll
            for (int off = 16; off > 0; off >>= 1) {
                p0 += __shfl_xor_sync(0xFFFFFFFFu, p0, off);
                p1 += __shfl_xor_sync(0xFFFFFFFFu, p1, off);
            }
            int pp = NQUAD & 1;
            if (lane == 0) {
                sred[((pp * 4 + 0) * 2 + half) * 4 + slot] = p0;
                sred[((pp * 4 + 1) * 2 + half) * 4 + slot] = p1;
            }
            __syncthreads();
            float bp0 = sred[((pp * 4 + 0) * 2 + 0) * 4 + slot] + sred[((pp * 4 + 0) * 2 + 1) * 4 + slot];
            float bp1 = sred[((pp * 4 + 1) * 2 + 0) * 4 + slot] + sred[((pp * 4 + 1) * 2 + 1) * 4 + slot];
            float w0 = __expf(bp0), w1 = __expf(bp1);
            l += w0 + w1;
#pragma unroll
            for (int j = 0; j < 4; ++j) acc[j] += w0 * e0[j] + w1 * e1[j];
        }

        if (HAS_TAIL) {
            int n = NENT - 1;
            const float* ft = &sfeat[slot][n * FDIM];
            float e0[4];
#pragma unroll
            for (int j = 0; j < 4; ++j) {
                float a = breg[j];
#pragma unroll
                for (int f = 0; f < FDIM; ++f) a += ft[f] * wreg[j][f];
                e0[j] = fast_tanh(a);
            }
            float p0 = 0.f;
#pragma unroll
            for (int j = 0; j < 4; ++j) p0 += s[j] * e0[j];
#pragma unroll
            for (int off = 16; off > 0; off >>= 1)
                p0 += __shfl_xor_sync(0xFFFFFFFFu, p0, off);
            int pp = (NQUAD + 1) & 1;
            if (lane == 0) sred[((pp * 4 + 0) * 2 + half) * 4 + slot] = p0;
            __syncthreads();
            float bp0 = sred[((pp * 4 + 0) * 2 + 0) * 4 + slot] + sred[((pp * 4 + 0) * 2 + 1) * 4 + slot];
            float w0 = __expf(bp0);
            l += w0;
#pragma unroll
            for (int j = 0; j < 4; ++j) acc[j] += w0 * e0[j];
        }

        float inv = 1.f / l;
#pragma unroll
        for (int j = 0; j < 4; ++j) {
            float f = acc[j] * inv;
            int col = CAT_OFF + j * 64 + half * 32 + lane;
            __nv_bfloat16 h = __float2bfloat16(f);
            g_catH[(size_t)row * 1024 + col] = h;
            g_catL[(size_t)row * 1024 + col] = __float2bfloat16(f - __bfloat162float(h));
        }
        __syncthreads();   // protect sfeat/sred reuse across row iterations
    }
}

__global__ __launch_bounds__(256, 2)
void attn_all(const float* __restrict__ inputs, const float* __restrict__ S,
              const float* __restrict__ Wo, const float* __restrict__ bo,
              const float* __restrict__ Wb, const float* __restrict__ bb,
              const float* __restrict__ Wr, const float* __restrict__ br) {
    __shared__ float sfeat[4][208];
    __shared__ float sred[64];
    int grp = blockIdx.x >> 10;
    int bid = blockIdx.x & 1023;
    if (grp == 0)
        attn_body<N_OTHER, 10, OFF_OTHER, 0,   256>(inputs, S, Wo, bo, bid, sfeat, sred);
    else if (grp == 1)
        attn_body<N_BOX,   13, OFF_BOX,   256, 512>(inputs, S, Wb, bb, bid, sfeat, sred);
    else
        attn_body<N_RAMP,  12, OFF_RAMP,  512, 768>(inputs, S, Wr, br, bid, sfeat, sred);
}

// ---------------------------------------------------------------------------
extern "C" void kernel_launch(void* const* d_in, const int* in_sizes, int n_in,
                              void* d_out, int out_size) {
    const float* inputs     = (const float*)d_in[0];
    const float* W_self     = (const float*)d_in[1];
    const float* b_self     = (const float*)d_in[2];
    const float* W_other    = (const float*)d_in[3];
    const float* b_other    = (const float*)d_in[4];
    const float* W_box      = (const float*)d_in[5];
    const float* b_box      = (const float*)d_in[6];
    const float* W_ramp     = (const float*)d_in[7];
    const float* b_ramp     = (const float*)d_in[8];
    const float* corr_other = (const float*)d_in[9];
    const float* corr_box   = (const float*)d_in[10];
    const float* corr_ramp  = (const float*)d_in[11];
    const float* W_fc       = (const float*)d_in[12];
    const float* b_fc       = (const float*)d_in[13];
    const float* W_e1       = (const float*)d_in[14];
    const float* b_e1       = (const float*)d_in[15];
    const float* W_e2       = (const float*)d_in[16];
    const float* b_e2       = (const float*)d_in[17];
    float* out = (float*)d_out;

    __nv_bfloat16 *embH, *embL, *catH, *catL, *hH, *hL;
    __nv_bfloat16 *Bs1H, *Bs1L, *Be1H, *Be1L, *Be2H, *Be2L;
    float* S;
    cudaGetSymbolAddress((void**)&embH, g_embH);
    cudaGetSymbolAddress((void**)&embL, g_embL);
    cudaGetSymbolAddress((void**)&S,    g_S);
    cudaGetSymbolAddress((void**)&catH, g_catH);
    cudaGetSymbolAddress((void**)&catL, g_catL);
    cudaGetSymbolAddress((void**)&hH,   g_hH);
    cudaGetSymbolAddress((void**)&hL,   g_hL);
    cudaGetSymbolAddress((void**)&Bs1H, g_Bs1H);
    cudaGetSymbolAddress((void**)&Bs1L, g_Bs1L);
    cudaGetSymbolAddress((void**)&Be1H, g_Be1H);
    cudaGetSymbolAddress((void**)&Be1L, g_Be1L);
    cudaGetSymbolAddress((void**)&Be2H, g_Be2H);
    cudaGetSymbolAddress((void**)&Be2L, g_Be2L);

    cudaFuncSetAttribute(mma_gemm<0>, cudaFuncAttributeMaxDynamicSharedMemorySize, GEMM_SMEM);
    cudaFuncSetAttribute(mma_gemm<1>, cudaFuncAttributeMaxDynamicSharedMemorySize, GEMM_SMEM);
    cudaFuncSetAttribute(mma_gemm<2>, cudaFuncAttributeMaxDynamicSharedMemorySize, GEMM_SMEM);

    // One-time stream/event creation (no device memory involved).
    static cudaStream_t s1 = nullptr;
    static cudaEvent_t e0 = nullptr, ePack = nullptr, eSelf = nullptr, eGi = nullptr;
    if (s1 == nullptr) {
        cudaStreamCreateWithFlags(&s1, cudaStreamNonBlocking);
        cudaEventCreateWithFlags(&e0,    cudaEventDisableTiming);
        cudaEventCreateWithFlags(&ePack, cudaEventDisableTiming);
        cudaEventCreateWithFlags(&eSelf, cudaEventDisableTiming);
        cudaEventCreateWithFlags(&eGi,   cudaEventDisableTiming);
    }

    PackArgs pa;
    pa.W[0] = corr_other; pa.oh[0] = Bs1H + 0 * 65536; pa.ol[0] = Bs1L + 0 * 65536; pa.K[0] = 256;
    pa.W[1] = corr_box;   pa.oh[1] = Bs1H + 1 * 65536; pa.ol[1] = Bs1L + 1 * 65536; pa.K[1] = 256;
    pa.W[2] = corr_ramp;  pa.oh[2] = Bs1H + 2 * 65536; pa.ol[2] = Bs1L + 2 * 65536; pa.K[2] = 256;
    pa.W[3] = W_fc;       pa.oh[3] = Bs1H + 3 * 65536; pa.ol[3] = Bs1L + 3 * 65536; pa.K[3] = 256;
    pa.W[4] = W_e1;       pa.oh[4] = Be1H;             pa.ol[4] = Be1L;             pa.K[4] = 1024;
    pa.W[5] = W_e2;       pa.oh[5] = Be2H;             pa.ol[5] = Be2L;             pa.K[5] = 256;
    pa.start[0] = 0;   pa.start[1] = 64;  pa.start[2] = 128; pa.start[3] = 192;
    pa.start[4] = 256; pa.start[5] = 512; pa.start[6] = 576;

    // Fork s1 from the capture stream.
    cudaEventRecord(e0, 0);
    cudaStreamWaitEvent(s1, e0, 0);

    // s1: pack weights (independent of self embed)
    pack_all<<<576, dim3(32, 8), 0, s1>>>(pa);
    cudaEventRecord(ePack, s1);

    // s0: self embed
    self_kernel<<<B_SZ / 4, 256>>>(inputs, W_self, b_self);
    cudaEventRecord(eSelf, 0);

    // s1: gi part of stage1 (cols 768..1024) — needs pack (in-stream) + self
    cudaStreamWaitEvent(s1, eSelf, 0);
    mma_gemm<0><<<dim3(2, B_SZ / 128), 256, GEMM_SMEM, s1>>>(
        embH, embL, Bs1H, Bs1L, 256, /*nboff*/6, b_fc, S, catH, catL);
    cudaEventRecord(eGi, s1);

    // s0: S part of stage1 (cols 0..768) — needs pack
    cudaStreamWaitEvent(0, ePack, 0);
    mma_gemm<0><<<dim3(6, B_SZ / 128), 256, GEMM_SMEM>>>(
        embH, embL, Bs1H, Bs1L, 256, /*nboff*/0, b_fc, S, catH, catL);

    // s0: scalar attention (runs concurrently with s1's gi tail)
    attn_all<<<3072, 256>>>(inputs, S, W_other, b_other, W_box, b_box, W_ramp, b_ramp);

    // rejoin: e1 needs full cat (attn on s0, gi on s1)
    cudaStreamWaitEvent(0, eGi, 0);
    mma_gemm<1><<<dim3(2, B_SZ / 128), 256, GEMM_SMEM>>>(
        catH, catL, Be1H, Be1L, 1024, 0, b_e1, nullptr, hH, hL);
    mma_gemm<2><<<dim3(2, B_SZ / 128), 256, GEMM_SMEM>>>(
        hH, hL, Be2H, Be2L, 256, 0, b_e2, out, nullptr, nullptr);
}